// round 16
// baseline (speedup 1.0000x reference)
#include <cuda_runtime.h>

// T=4, B=2, L=2048, D=4096  -> per-timestep slice N = 2*2048*4096 = 16,777,216 floats
#define SLICE_N   (2 * 2048 * 4096)
#define SLICE_N4  (SLICE_N / 4)   // 4,194,304 float4 per slice

// silu(x) = x * sigmoid(x) = 0.5*x*(1 + tanh(x/2))
// HW tanh (MUFU.TANH): 1 MUFU op per element instead of 2 (EX2+RCP).
__device__ __forceinline__ float silu1(float v) {
    float t;
    asm("tanh.approx.f32 %0, %1;" : "=f"(t) : "f"(0.5f * v));
    return 0.5f * v * (1.0f + t);
}

__device__ __forceinline__ float4 silu4(float4 v) {
    float4 r;
    r.x = silu1(v.x);
    r.y = silu1(v.y);
    r.z = silu1(v.z);
    r.w = silu1(v.w);
    return r;
}

__device__ __forceinline__ float4 add4(float4 a, float4 b) {
    return make_float4(a.x + b.x, a.y + b.y, a.z + b.z, a.w + b.w);
}

__device__ __forceinline__ float4 sub4(float4 a, float4 b) {
    return make_float4(a.x - b.x, a.y - b.y, a.z - b.z, a.w - b.w);
}

// FINAL (converged, 8-run stable: kernel 74.1-75.8us, e2e 81.95-82.02us):
// exact-fit grid, one float4 column per thread, 4 front-batched coalesced
// LDG.128, stores interleaved with compute, single MUFU.TANH per element.
// 537 MB compulsory traffic @ ~7.2 TB/s app-level = ~90% of HBM3e spec —
// the 50/50 read/write turnaround ceiling. All SM-side levers falsified by
// single-variable experiments (persistence, MLP, L2 policy, store order,
// block size, MUFU pressure); issue slots 83% idle -> bottleneck is HBM.
__global__ void __launch_bounds__(128, 1)
actswl_kernel(const float4* __restrict__ x, float4* __restrict__ out) {
    const int i = blockIdx.x * 128 + threadIdx.x;

    // Front-batch all 4 global loads (64 MB apart, each coalesced within its slice).
    const float4 a0 = x[i];
    const float4 a1 = x[i + SLICE_N4];
    const float4 a2 = x[i + 2 * SLICE_N4];
    const float4 a3 = x[i + 3 * SLICE_N4];

    // t = 0
    float4 X  = a0;
    float4 y0 = silu4(X);
    out[i] = y0;

    // t = 1
    X = add4(X, a1);
    float4 y1 = silu4(X);
    out[i + SLICE_N4] = sub4(y1, y0);

    // t = 2
    X = add4(X, a2);
    float4 y2 = silu4(X);
    out[i + 2 * SLICE_N4] = sub4(y2, y1);

    // t = 3
    X = add4(X, a3);
    float4 y3 = silu4(X);
    out[i + 3 * SLICE_N4] = sub4(y3, y2);
}

extern "C" void kernel_launch(void* const* d_in, const int* in_sizes, int n_in,
                              void* d_out, int out_size) {
    const float4* x = (const float4*)d_in[0];
    float4* out = (float4*)d_out;

    const int blocks = SLICE_N4 / 128;  // 32768 blocks, exact fit
    actswl_kernel<<<blocks, 128>>>(x, out);
}

// round 17
// speedup vs baseline: 1.0031x; 1.0031x over previous
#include <cuda_runtime.h>

// T=4, B=2, L=2048, D=4096  -> per-timestep slice N = 2*2048*4096 = 16,777,216 floats
#define SLICE_N   (2 * 2048 * 4096)
#define SLICE_N4  (SLICE_N / 4)   // 4,194,304 float4 per slice

// silu(x) = x * sigmoid(x) = 0.5*x*(1 + tanh(x/2))
// HW tanh (MUFU.TANH): 1 MUFU op per element instead of 2 (EX2+RCP).
__device__ __forceinline__ float silu1(float v) {
    float t;
    asm("tanh.approx.f32 %0, %1;" : "=f"(t) : "f"(0.5f * v));
    return 0.5f * v * (1.0f + t);
}

__device__ __forceinline__ float4 silu4(float4 v) {
    float4 r;
    r.x = silu1(v.x);
    r.y = silu1(v.y);
    r.z = silu1(v.z);
    r.w = silu1(v.w);
    return r;
}

__device__ __forceinline__ float4 add4(float4 a, float4 b) {
    return make_float4(a.x + b.x, a.y + b.y, a.z + b.z, a.w + b.w);
}

__device__ __forceinline__ float4 sub4(float4 a, float4 b) {
    return make_float4(a.x - b.x, a.y - b.y, a.z - b.z, a.w - b.w);
}

// FINAL (converged, 9-run stable: kernel 74.1-75.8us, e2e 81.95-82.02us):
// exact-fit grid, one float4 column per thread, 4 front-batched coalesced
// LDG.128, stores interleaved with compute, single MUFU.TANH per element.
// 537 MB compulsory traffic @ ~7.2 TB/s app-level = ~90% of HBM3e spec —
// the 50/50 read/write turnaround ceiling. All SM-side levers falsified by
// single-variable experiments (persistence, MLP, L2 policy, store order,
// block size, MUFU pressure); issue slots 83% idle -> bottleneck is HBM.
__global__ void __launch_bounds__(128, 1)
actswl_kernel(const float4* __restrict__ x, float4* __restrict__ out) {
    const int i = blockIdx.x * 128 + threadIdx.x;

    // Front-batch all 4 global loads (64 MB apart, each coalesced within its slice).
    const float4 a0 = x[i];
    const float4 a1 = x[i + SLICE_N4];
    const float4 a2 = x[i + 2 * SLICE_N4];
    const float4 a3 = x[i + 3 * SLICE_N4];

    // t = 0
    float4 X  = a0;
    float4 y0 = silu4(X);
    out[i] = y0;

    // t = 1
    X = add4(X, a1);
    float4 y1 = silu4(X);
    out[i + SLICE_N4] = sub4(y1, y0);

    // t = 2
    X = add4(X, a2);
    float4 y2 = silu4(X);
    out[i + 2 * SLICE_N4] = sub4(y2, y1);

    // t = 3
    X = add4(X, a3);
    float4 y3 = silu4(X);
    out[i + 3 * SLICE_N4] = sub4(y3, y2);
}

extern "C" void kernel_launch(void* const* d_in, const int* in_sizes, int n_in,
                              void* d_out, int out_size) {
    const float4* x = (const float4*)d_in[0];
    float4* out = (float4*)d_out;

    const int blocks = SLICE_N4 / 128;  // 32768 blocks, exact fit
    actswl_kernel<<<blocks, 128>>>(x, out);
}